// round 13
// baseline (speedup 1.0000x reference)
#include <cuda_runtime.h>
#include <cstdint>

#define NMAX 50000
#define EMAX 800000
#define ESLMAX (NMAX + EMAX)
#define F 128
#define NH 4
#define WTF_SZ (4 * 128 * 36)

// ---------------- scratch ----------------
__device__ float    g_h[NMAX * F];        // h (f32) for agg gathers
__device__ uint32_t g_xtf[NMAX * F];      // x   as tf32, phys layout [row][kt*32+ph]
__device__ uint32_t g_acttf[NMAX * F];    // act as tf32, phys layout
__device__ float    g_s[NMAX * 8];        // s_src[4], s_dst[4]
__device__ int      g_cnt[NMAX];          // zero at load; scan3 re-zeroes
__device__ int      g_inc[NMAX];
__device__ int      g_tile[64];
__device__ int      g_off[NMAX + 1];
__device__ int      g_cur[NMAX];
__device__ int      g_csr[ESLMAX];
__device__ uint32_t g_Wtf1[WTF_SZ];       // W1 tf32 pre-swizzled [kt][n][36]
__device__ uint32_t g_Wtf2[WTF_SZ];

__device__ __forceinline__ float lrelu(float x) { return x > 0.f ? x : 0.2f * x; }
__device__ __forceinline__ uint32_t f2tf(float f) {
    uint32_t r; asm("cvt.rna.tf32.f32 %0, %1;" : "=r"(r) : "f"(f)); return r;
}
__device__ __forceinline__ void mma_tf32(float* d, uint32_t a0, uint32_t a1,
                                         uint32_t a2, uint32_t a3,
                                         uint32_t b0, uint32_t b1)
{
    asm volatile(
        "mma.sync.aligned.m16n8k8.row.col.f32.tf32.tf32.f32 "
        "{%0,%1,%2,%3}, {%4,%5,%6,%7}, {%8,%9}, {%0,%1,%2,%3};"
        : "+f"(d[0]), "+f"(d[1]), "+f"(d[2]), "+f"(d[3])
        : "r"(a0), "r"(a1), "r"(a2), "r"(a3), "r"(b0), "r"(b1));
}

// ---------------- W pre-convert: f32 [k][n] -> tf32 swizzled [kt][n][36] ----------------
__global__ void wconv_kernel(const float* __restrict__ W1,
                             const float* __restrict__ W2)
{
    int idx = blockIdx.x * 256 + threadIdx.x;   // 0 .. 32767
    int layer = idx >> 14;
    int rem = idx & 16383;
    int kg = rem >> 7, nn = rem & 127;
    const float* W = layer ? W2 : W1;
    float v = W[kg * 128 + nn];
    int kt = kg >> 5, k = kg & 31;
    int ph = (k & 3) * 8 + ((k >> 3) << 1) + ((k >> 2) & 1);
    uint32_t* buf = layer ? g_Wtf2 : g_Wtf1;
    buf[kt * 128 * 36 + nn * 36 + ph] = f2tf(v);
}

// ---------------- x pre-convert: f32 [row][k] -> tf32 phys [row][kt*32+ph] ----------------
__global__ void xconv_kernel(const float* __restrict__ x, int n)
{
    int idx = blockIdx.x * 256 + threadIdx.x;
    if (idx >= n * 32) return;
    int row = idx >> 5, q = idx & 31;
    float4 v = *(const float4*)(x + (size_t)row * F + q * 4);
    int col = q * 4;
    int kk = col & 31, kt = col >> 5;
    int base = ((kk >> 3) << 1) | ((kk >> 2) & 1);
    uint32_t* p = g_xtf + (size_t)row * F + kt * 32 + base;
    p[0] = f2tf(v.x); p[8] = f2tf(v.y); p[16] = f2tf(v.z); p[24] = f2tf(v.w);
}

// ---------------- tf32 tensor-core GEMM (m128 x n128), pure-copy fills ----------------
__global__ __launch_bounds__(256, 2)
void gemm128_tc_kernel(const uint32_t* __restrict__ Atf,
                       const uint32_t* __restrict__ Wtf,
                       const float* __restrict__ asrc,
                       const float* __restrict__ adst, int n)
{
    __shared__ uint32_t As[128 * 36];   // 18.4 KB
    __shared__ uint32_t Bs[128 * 36];   // 18.4 KB

    int tid  = threadIdx.x;
    int warp = tid >> 5, lane = tid & 31;
    int wm = warp >> 1, wn = warp & 1;    // 4x2 warps, warp tile m32 x n64
    int g = lane >> 2, t = lane & 3;
    int row0 = blockIdx.x * 128;

    float acc[2][8][4];
#pragma unroll
    for (int mf = 0; mf < 2; mf++)
#pragma unroll
        for (int i = 0; i < 8; i++)
#pragma unroll
            for (int j = 0; j < 4; j++) acc[mf][i][j] = 0.f;

    for (int kt = 0; kt < 4; kt++) {
        // As fill: pure uint4 copy from pre-converted tf32
#pragma unroll
        for (int it = 0; it < 4; it++) {
            int task = tid + it * 256;
            int r = task >> 3, q = task & 7;
            int grow = row0 + r;
            uint4 v = make_uint4(0u, 0u, 0u, 0u);
            if (grow < n) v = *(const uint4*)&Atf[(size_t)grow * F + kt * 32 + q * 4];
            *(uint4*)&As[r * 36 + q * 4] = v;
        }
        // Bs fill: pure uint4 copy from pre-swizzled W
#pragma unroll
        for (int it = 0; it < 4; it++) {
            int task = tid + it * 256;
            int nr = task >> 3, q = task & 7;
            *(uint4*)&Bs[nr * 36 + q * 4] =
                *(const uint4*)&Wtf[kt * 128 * 36 + nr * 36 + q * 4];
        }
        __syncthreads();

        int ra0 = wm * 32 + g;
        uint4 Aa[2][4];
#pragma unroll
        for (int mf = 0; mf < 2; mf++) {
            int ra = ra0 + mf * 16;
            Aa[mf][0] = *(uint4*)&As[ra * 36 + t * 8];
            Aa[mf][1] = *(uint4*)&As[ra * 36 + t * 8 + 4];
            Aa[mf][2] = *(uint4*)&As[(ra + 8) * 36 + t * 8];
            Aa[mf][3] = *(uint4*)&As[(ra + 8) * 36 + t * 8 + 4];
        }
#pragma unroll
        for (int nt = 0; nt < 8; nt++) {
            int nb = wn * 64 + nt * 8 + g;
            uint4 B1 = *(uint4*)&Bs[nb * 36 + t * 8];
            uint4 B2 = *(uint4*)&Bs[nb * 36 + t * 8 + 4];
#pragma unroll
            for (int mf = 0; mf < 2; mf++) {
                mma_tf32(acc[mf][nt], Aa[mf][0].x, Aa[mf][2].x, Aa[mf][0].y, Aa[mf][2].y, B1.x, B1.y);
                mma_tf32(acc[mf][nt], Aa[mf][0].z, Aa[mf][2].z, Aa[mf][0].w, Aa[mf][2].w, B1.z, B1.w);
                mma_tf32(acc[mf][nt], Aa[mf][1].x, Aa[mf][3].x, Aa[mf][1].y, Aa[mf][3].y, B2.x, B2.y);
                mma_tf32(acc[mf][nt], Aa[mf][1].z, Aa[mf][3].z, Aa[mf][1].w, Aa[mf][3].w, B2.z, B2.w);
            }
        }
        __syncthreads();
    }

    // epilogue: store h (f32) + fused attention scores
#pragma unroll
    for (int mf = 0; mf < 2; mf++) {
        int r_lo = row0 + wm * 32 + mf * 16 + g;
        int r_hi = r_lo + 8;
        float ps[2][2] = {{0.f, 0.f}, {0.f, 0.f}};
        float pd[2][2] = {{0.f, 0.f}, {0.f, 0.f}};
#pragma unroll
        for (int nt = 0; nt < 8; nt++) {
            int col = wn * 64 + nt * 8 + 2 * t;
            int hl = nt >> 2;
            float a0s = __ldg(asrc + col), a1s = __ldg(asrc + col + 1);
            float a0d = __ldg(adst + col), a1d = __ldg(adst + col + 1);
            ps[0][hl] += acc[mf][nt][0] * a0s + acc[mf][nt][1] * a1s;
            pd[0][hl] += acc[mf][nt][0] * a0d + acc[mf][nt][1] * a1d;
            ps[1][hl] += acc[mf][nt][2] * a0s + acc[mf][nt][3] * a1s;
            pd[1][hl] += acc[mf][nt][2] * a0d + acc[mf][nt][3] * a1d;
            if (r_lo < n)
                *(float2*)(g_h + (size_t)r_lo * F + col) = make_float2(acc[mf][nt][0], acc[mf][nt][1]);
            if (r_hi < n)
                *(float2*)(g_h + (size_t)r_hi * F + col) = make_float2(acc[mf][nt][2], acc[mf][nt][3]);
        }
#pragma unroll
        for (int off = 1; off <= 2; off <<= 1) {
#pragma unroll
            for (int i = 0; i < 2; i++)
#pragma unroll
                for (int j = 0; j < 2; j++) {
                    ps[i][j] += __shfl_xor_sync(0xffffffffu, ps[i][j], off);
                    pd[i][j] += __shfl_xor_sync(0xffffffffu, pd[i][j], off);
                }
        }
        if (t == 0) {
            int h0 = wn * 2;
            if (r_lo < n) {
                g_s[(size_t)r_lo * 8 + h0]     = ps[0][0];
                g_s[(size_t)r_lo * 8 + h0 + 1] = ps[0][1];
                g_s[(size_t)r_lo * 8 + 4 + h0]     = pd[0][0];
                g_s[(size_t)r_lo * 8 + 4 + h0 + 1] = pd[0][1];
            }
            if (r_hi < n) {
                g_s[(size_t)r_hi * 8 + h0]     = ps[1][0];
                g_s[(size_t)r_hi * 8 + h0 + 1] = ps[1][1];
                g_s[(size_t)r_hi * 8 + 4 + h0]     = pd[1][0];
                g_s[(size_t)r_hi * 8 + 4 + h0 + 1] = pd[1][1];
            }
        }
    }
}

// ---------------- CSR build ----------------
__global__ void cnt_edges_kernel(const int* __restrict__ dst, int e)
{
    int i = blockIdx.x * blockDim.x + threadIdx.x;
    if (i < e) atomicAdd(&g_cnt[dst[i]], 1);
}
__global__ void scan1_kernel(int n)
{
    __shared__ int sm[1024];
    int gid = blockIdx.x * 1024 + threadIdx.x;
    int v = (gid < n) ? g_cnt[gid] : 0;
    sm[threadIdx.x] = v;
    __syncthreads();
    for (int off = 1; off < 1024; off <<= 1) {
        int tv = (threadIdx.x >= off) ? sm[threadIdx.x - off] : 0;
        __syncthreads();
        sm[threadIdx.x] += tv;
        __syncthreads();
    }
    if (gid < n) g_inc[gid] = sm[threadIdx.x];
    if (threadIdx.x == 1023) g_tile[blockIdx.x] = sm[1023];
}
__global__ void scan3_kernel(int n)
{
    __shared__ int sm[64];
    int mytile = blockIdx.x >> 2;
    int t = threadIdx.x;
    if (t < 64) sm[t] = (t < mytile) ? g_tile[t] : 0;
    __syncthreads();
    if (t < 32) sm[t] += sm[t + 32];
    __syncthreads();
    if (t < 16) sm[t] += sm[t + 16];
    __syncthreads();
    if (t < 8) sm[t] += sm[t + 8];
    __syncthreads();
    if (t < 4) sm[t] += sm[t + 4];
    __syncthreads();
    if (t < 2) sm[t] += sm[t + 2];
    __syncthreads();
    if (t == 0) sm[0] += sm[1];
    __syncthreads();
    int prefix = sm[0];

    int gid = blockIdx.x * blockDim.x + t;
    if (gid < n) {
        int cnt = g_cnt[gid];
        g_cnt[gid] = 0;                      // restore invariant for next replay
        int val = g_inc[gid] + prefix + gid + 1;   // +gid+1: one self-loop/node
        g_off[gid + 1] = val;
        g_cur[gid] = val - 1 - cnt;
        g_csr[val - 1] = gid;                // self-loop slot
    }
    if (gid == 0) g_off[0] = 0;
}
__global__ void fill_kernel(const int* __restrict__ src,
                            const int* __restrict__ dst, int e)
{
    int i = blockIdx.x * blockDim.x + threadIdx.x;
    if (i >= e) return;
    int pos = atomicAdd(&g_cur[dst[i]], 1);
    g_csr[pos] = src[i];
}

// ---------------- fused softmax + aggregation ----------------
// mode 0: g_acttf = tf32-phys(relu(agg + b))   (layer 1 -> GEMM2 input)
// mode 1: out = relu(agg + b) . lw + lb        (layer 2 + readout)
__global__ void agg_kernel(const float* __restrict__ b,
                           const float* __restrict__ lw,
                           const float* __restrict__ lb,
                           float* __restrict__ out, int n, int mode)
{
    int w = (blockIdx.x * blockDim.x + threadIdx.x) >> 5;
    int lane = threadIdx.x & 31;
    if (w >= n) return;
    int beg = g_off[w], end = g_off[w + 1];
    int head = lane >> 3;
    float sdh = g_s[(size_t)w * 8 + 4 + head];

    float4 acc = make_float4(0.f, 0.f, 0.f, 0.f);
    float z = 0.f;
#pragma unroll 4
    for (int i = beg; i < end; i++) {
        int u = __ldg(&g_csr[i]);
        float ssh = __ldg(&g_s[(size_t)u * 8 + head]);
        float p = __expf(lrelu(ssh + sdh));
        float4 hv = __ldg((const float4*)(g_h + (size_t)u * F + lane * 4));
        acc.x += p * hv.x; acc.y += p * hv.y;
        acc.z += p * hv.z; acc.w += p * hv.w;
        z += p;
    }
    float inv = 1.f / (z + 1e-16f);
    int col = lane * 4;
    if (mode == 0) {
        float ox = fmaxf(acc.x * inv + b[col], 0.f);
        float oy = fmaxf(acc.y * inv + b[col + 1], 0.f);
        float oz = fmaxf(acc.z * inv + b[col + 2], 0.f);
        float ow = fmaxf(acc.w * inv + b[col + 3], 0.f);
        int kk = col & 31, kt = col >> 5;
        int base = ((kk >> 3) << 1) | ((kk >> 2) & 1);
        uint32_t* p = g_acttf + (size_t)w * F + kt * 32 + base;
        p[0] = f2tf(ox); p[8] = f2tf(oy); p[16] = f2tf(oz); p[24] = f2tf(ow);
    } else {
        float4 bb = *(const float4*)(b + col);
        float4 ww = *(const float4*)(lw + col);
        float s = fmaxf(acc.x * inv + bb.x, 0.f) * ww.x +
                  fmaxf(acc.y * inv + bb.y, 0.f) * ww.y +
                  fmaxf(acc.z * inv + bb.z, 0.f) * ww.z +
                  fmaxf(acc.w * inv + bb.w, 0.f) * ww.w;
        for (int off = 16; off; off >>= 1)
            s += __shfl_xor_sync(0xffffffffu, s, off);
        if (lane == 0) out[w] = s + lb[0];
    }
}

// ---------------- launch ----------------
// Launch #4 (the slot ncu profiles) = gemm128_tc_kernel (layer 1).
extern "C" void kernel_launch(void* const* d_in, const int* in_sizes, int n_in,
                              void* d_out, int out_size)
{
    const float* x   = (const float*)d_in[0];
    const int*   src = (const int*)d_in[1];
    const int*   dst = (const int*)d_in[2];
    const float* W1  = (const float*)d_in[3];
    const float* as1 = (const float*)d_in[4];
    const float* ad1 = (const float*)d_in[5];
    const float* b1  = (const float*)d_in[6];
    const float* W2  = (const float*)d_in[7];
    const float* as2 = (const float*)d_in[8];
    const float* ad2 = (const float*)d_in[9];
    const float* b2  = (const float*)d_in[10];
    const float* lw  = (const float*)d_in[11];
    const float* lb  = (const float*)d_in[12];
    float* out = (float*)d_out;

    int n = in_sizes[0] / F;
    int e = in_sizes[1];

    int nb256 = (n + 255) / 256;
    int eb256 = (e + 255) / 256;
    int ntiles = (n + 1023) / 1024;
    int gemm_blocks = (n + 127) / 128;
    int warp_blocks = (int)(((size_t)n * 32 + 255) / 256);
    int xconv_blocks = (n * 32 + 255) / 256;

    uint32_t* xtf;  cudaGetSymbolAddress((void**)&xtf, g_xtf);
    uint32_t* atf;  cudaGetSymbolAddress((void**)&atf, g_acttf);
    uint32_t* wtf1; cudaGetSymbolAddress((void**)&wtf1, g_Wtf1);
    uint32_t* wtf2; cudaGetSymbolAddress((void**)&wtf2, g_Wtf2);

    wconv_kernel<<<128, 256>>>(W1, W2);                              // 1
    xconv_kernel<<<xconv_blocks, 256>>>(x, n);                       // 2
    cnt_edges_kernel<<<eb256, 256>>>(dst, e);                        // 3
    gemm128_tc_kernel<<<gemm_blocks, 256>>>(xtf, wtf1, as1, ad1, n); // 4 <- profiled
    scan1_kernel<<<ntiles, 1024>>>(n);                               // 5
    scan3_kernel<<<nb256, 256>>>(n);                                 // 6
    fill_kernel<<<eb256, 256>>>(src, dst, e);                        // 7
    agg_kernel<<<warp_blocks, 256>>>(b1, nullptr, nullptr, nullptr, n, 0);  // 8
    gemm128_tc_kernel<<<gemm_blocks, 256>>>(atf, wtf2, as2, ad2, n); // 9
    agg_kernel<<<warp_blocks, 256>>>(b2, lw, lb, out, n, 1);         // 10
}

// round 14
// speedup vs baseline: 1.0385x; 1.0385x over previous
#include <cuda_runtime.h>
#include <cstdint>

#define NMAX 50000
#define NPAD (NMAX + 128)
#define EMAX 800000
#define ESLMAX (NMAX + EMAX)
#define F 128
#define NH 4
#define WTF_SZ (4 * 128 * 32)

// ---------------- scratch ----------------
__device__ float    g_h[NMAX * F];        // h (f32) for agg gathers
__device__ uint32_t g_xtf[NPAD * F];      // x   tf32 phys [row][kt*32+ph] (padded rows read as 0)
__device__ uint32_t g_acttf[NPAD * F];    // act tf32 phys
__device__ float    g_s[NMAX * 8];        // s_src[4], s_dst[4]
__device__ int      g_cnt[NMAX];          // zero at load; scan3 re-zeroes
__device__ int      g_inc[NMAX];
__device__ int      g_tile[64];
__device__ int      g_off[NMAX + 1];
__device__ int      g_cur[NMAX];
__device__ int      g_csr[ESLMAX];
__device__ uint32_t g_Wtf1[WTF_SZ];       // W1 tf32 [kt][n][32] phys
__device__ uint32_t g_Wtf2[WTF_SZ];

__device__ __forceinline__ float lrelu(float x) { return x > 0.f ? x : 0.2f * x; }
__device__ __forceinline__ uint32_t f2tf(float f) {
    uint32_t r; asm("cvt.rna.tf32.f32 %0, %1;" : "=r"(r) : "f"(f)); return r;
}
__device__ __forceinline__ void mma_tf32(float* d, uint32_t a0, uint32_t a1,
                                         uint32_t a2, uint32_t a3,
                                         uint32_t b0, uint32_t b1)
{
    asm volatile(
        "mma.sync.aligned.m16n8k8.row.col.f32.tf32.tf32.f32 "
        "{%0,%1,%2,%3}, {%4,%5,%6,%7}, {%8,%9}, {%0,%1,%2,%3};"
        : "+f"(d[0]), "+f"(d[1]), "+f"(d[2]), "+f"(d[3])
        : "r"(a0), "r"(a1), "r"(a2), "r"(a3), "r"(b0), "r"(b1));
}

// ---------------- W pre-convert: f32 [k][n] -> tf32 phys [kt][n][32] ----------------
__global__ void wconv_kernel(const float* __restrict__ W1,
                             const float* __restrict__ W2)
{
    int idx = blockIdx.x * 256 + threadIdx.x;   // 0 .. 32767
    int layer = idx >> 14;
    int rem = idx & 16383;
    int kg = rem >> 7, nn = rem & 127;
    const float* W = layer ? W2 : W1;
    float v = W[kg * 128 + nn];
    int kt = kg >> 5, k = kg & 31;
    int ph = (k & 3) * 8 + ((k >> 3) << 1) + ((k >> 2) & 1);
    uint32_t* buf = layer ? g_Wtf2 : g_Wtf1;
    buf[kt * 128 * 32 + nn * 32 + ph] = f2tf(v);
}

// ---------------- x pre-convert: f32 [row][k] -> tf32 phys [row][kt*32+ph] ----------------
__global__ void xconv_kernel(const float* __restrict__ x, int n)
{
    int idx = blockIdx.x * 256 + threadIdx.x;
    if (idx >= n * 32) return;
    int row = idx >> 5, q = idx & 31;
    float4 v = *(const float4*)(x + (size_t)row * F + q * 4);
    int col = q * 4;
    int kk = col & 31, kt = col >> 5;
    int base = ((kk >> 3) << 1) | ((kk >> 2) & 1);
    uint32_t* p = g_xtf + (size_t)row * F + kt * 32 + base;
    p[0] = f2tf(v.x); p[8] = f2tf(v.y); p[16] = f2tf(v.z); p[24] = f2tf(v.w);
}

// ---------------- tf32 GEMM, smem-free: fragments via direct LDG.128 ----------------
__global__ __launch_bounds__(256, 2)
void gemm128_tc_kernel(const uint32_t* __restrict__ Atf,
                       const uint32_t* __restrict__ Wtf,
                       const float* __restrict__ asrc,
                       const float* __restrict__ adst, int n)
{
    int tid  = threadIdx.x;
    int warp = tid >> 5, lane = tid & 31;
    int wm = warp >> 1, wn = warp & 1;    // 4x2 warps, warp tile m32 x n64
    int g = lane >> 2, t = lane & 3;
    int row0 = blockIdx.x * 128;

    float acc[2][8][4];
#pragma unroll
    for (int mf = 0; mf < 2; mf++)
#pragma unroll
        for (int i = 0; i < 8; i++)
#pragma unroll
            for (int j = 0; j < 4; j++) acc[mf][i][j] = 0.f;

    // per-lane base pointers (rows beyond n hit zero-padded NPAD region)
    const uint32_t* Abase = Atf + (size_t)(row0 + wm * 32 + g) * F + t * 8;
    const uint32_t* Bbase = Wtf + (size_t)(wn * 64 + g) * 32 + t * 8;

#pragma unroll
    for (int kt = 0; kt < 4; kt++) {
        uint4 Aa[2][4];
#pragma unroll
        for (int mf = 0; mf < 2; mf++) {
            const uint32_t* ap = Abase + mf * 16 * F + kt * 32;
            Aa[mf][0] = *(const uint4*)(ap);
            Aa[mf][1] = *(const uint4*)(ap + 4);
            Aa[mf][2] = *(const uint4*)(ap + 8 * F);
            Aa[mf][3] = *(const uint4*)(ap + 8 * F + 4);
        }
#pragma unroll
        for (int nt = 0; nt < 8; nt++) {
            const uint32_t* bp = Bbase + kt * 4096 + nt * 8 * 32;
            uint4 B1 = *(const uint4*)(bp);
            uint4 B2 = *(const uint4*)(bp + 4);
#pragma unroll
            for (int mf = 0; mf < 2; mf++) {
                mma_tf32(acc[mf][nt], Aa[mf][0].x, Aa[mf][2].x, Aa[mf][0].y, Aa[mf][2].y, B1.x, B1.y);
                mma_tf32(acc[mf][nt], Aa[mf][0].z, Aa[mf][2].z, Aa[mf][0].w, Aa[mf][2].w, B1.z, B1.w);
                mma_tf32(acc[mf][nt], Aa[mf][1].x, Aa[mf][3].x, Aa[mf][1].y, Aa[mf][3].y, B2.x, B2.y);
                mma_tf32(acc[mf][nt], Aa[mf][1].z, Aa[mf][3].z, Aa[mf][1].w, Aa[mf][3].w, B2.z, B2.w);
            }
        }
    }

    // epilogue: store h (f32) + fused attention scores
#pragma unroll
    for (int mf = 0; mf < 2; mf++) {
        int r_lo = row0 + wm * 32 + mf * 16 + g;
        int r_hi = r_lo + 8;
        float ps[2][2] = {{0.f, 0.f}, {0.f, 0.f}};
        float pd[2][2] = {{0.f, 0.f}, {0.f, 0.f}};
#pragma unroll
        for (int nt = 0; nt < 8; nt++) {
            int col = wn * 64 + nt * 8 + 2 * t;
            int hl = nt >> 2;
            float a0s = __ldg(asrc + col), a1s = __ldg(asrc + col + 1);
            float a0d = __ldg(adst + col), a1d = __ldg(adst + col + 1);
            ps[0][hl] += acc[mf][nt][0] * a0s + acc[mf][nt][1] * a1s;
            pd[0][hl] += acc[mf][nt][0] * a0d + acc[mf][nt][1] * a1d;
            ps[1][hl] += acc[mf][nt][2] * a0s + acc[mf][nt][3] * a1s;
            pd[1][hl] += acc[mf][nt][2] * a0d + acc[mf][nt][3] * a1d;
            if (r_lo < n)
                *(float2*)(g_h + (size_t)r_lo * F + col) = make_float2(acc[mf][nt][0], acc[mf][nt][1]);
            if (r_hi < n)
                *(float2*)(g_h + (size_t)r_hi * F + col) = make_float2(acc[mf][nt][2], acc[mf][nt][3]);
        }
#pragma unroll
        for (int off = 1; off <= 2; off <<= 1) {
#pragma unroll
            for (int i = 0; i < 2; i++)
#pragma unroll
                for (int j = 0; j < 2; j++) {
                    ps[i][j] += __shfl_xor_sync(0xffffffffu, ps[i][j], off);
                    pd[i][j] += __shfl_xor_sync(0xffffffffu, pd[i][j], off);
                }
        }
        if (t == 0) {
            int h0 = wn * 2;
            if (r_lo < n) {
                g_s[(size_t)r_lo * 8 + h0]     = ps[0][0];
                g_s[(size_t)r_lo * 8 + h0 + 1] = ps[0][1];
                g_s[(size_t)r_lo * 8 + 4 + h0]     = pd[0][0];
                g_s[(size_t)r_lo * 8 + 4 + h0 + 1] = pd[0][1];
            }
            if (r_hi < n) {
                g_s[(size_t)r_hi * 8 + h0]     = ps[1][0];
                g_s[(size_t)r_hi * 8 + h0 + 1] = ps[1][1];
                g_s[(size_t)r_hi * 8 + 4 + h0]     = pd[1][0];
                g_s[(size_t)r_hi * 8 + 4 + h0 + 1] = pd[1][1];
            }
        }
    }
}

// ---------------- CSR build ----------------
__global__ void cnt_edges_kernel(const int* __restrict__ dst, int e)
{
    int i = blockIdx.x * blockDim.x + threadIdx.x;
    if (i < e) atomicAdd(&g_cnt[dst[i]], 1);
}
__global__ void scan1_kernel(int n)
{
    __shared__ int sm[1024];
    int gid = blockIdx.x * 1024 + threadIdx.x;
    int v = (gid < n) ? g_cnt[gid] : 0;
    sm[threadIdx.x] = v;
    __syncthreads();
    for (int off = 1; off < 1024; off <<= 1) {
        int tv = (threadIdx.x >= off) ? sm[threadIdx.x - off] : 0;
        __syncthreads();
        sm[threadIdx.x] += tv;
        __syncthreads();
    }
    if (gid < n) g_inc[gid] = sm[threadIdx.x];
    if (threadIdx.x == 1023) g_tile[blockIdx.x] = sm[1023];
}
__global__ void scan3_kernel(int n)
{
    __shared__ int sm[64];
    int mytile = blockIdx.x >> 2;
    int t = threadIdx.x;
    if (t < 64) sm[t] = (t < mytile) ? g_tile[t] : 0;
    __syncthreads();
    if (t < 32) sm[t] += sm[t + 32];
    __syncthreads();
    if (t < 16) sm[t] += sm[t + 16];
    __syncthreads();
    if (t < 8) sm[t] += sm[t + 8];
    __syncthreads();
    if (t < 4) sm[t] += sm[t + 4];
    __syncthreads();
    if (t < 2) sm[t] += sm[t + 2];
    __syncthreads();
    if (t == 0) sm[0] += sm[1];
    __syncthreads();
    int prefix = sm[0];

    int gid = blockIdx.x * blockDim.x + t;
    if (gid < n) {
        int cnt = g_cnt[gid];
        g_cnt[gid] = 0;                      // restore invariant for next replay
        int val = g_inc[gid] + prefix + gid + 1;   // +gid+1: one self-loop/node
        g_off[gid + 1] = val;
        g_cur[gid] = val - 1 - cnt;
        g_csr[val - 1] = gid;                // self-loop slot
    }
    if (gid == 0) g_off[0] = 0;
}
__global__ void fill_kernel(const int* __restrict__ src,
                            const int* __restrict__ dst, int e)
{
    int i = blockIdx.x * blockDim.x + threadIdx.x;
    if (i >= e) return;
    int pos = atomicAdd(&g_cur[dst[i]], 1);
    g_csr[pos] = src[i];
}

// ---------------- fused softmax + aggregation ----------------
// mode 0: g_acttf = tf32-phys(relu(agg + b))   (layer 1 -> GEMM2 input)
// mode 1: out = relu(agg + b) . lw + lb        (layer 2 + readout)
__global__ void agg_kernel(const float* __restrict__ b,
                           const float* __restrict__ lw,
                           const float* __restrict__ lb,
                           float* __restrict__ out, int n, int mode)
{
    int w = (blockIdx.x * blockDim.x + threadIdx.x) >> 5;
    int lane = threadIdx.x & 31;
    if (w >= n) return;
    int beg = g_off[w], end = g_off[w + 1];
    int head = lane >> 3;
    float sdh = g_s[(size_t)w * 8 + 4 + head];

    float4 acc = make_float4(0.f, 0.f, 0.f, 0.f);
    float z = 0.f;
#pragma unroll 4
    for (int i = beg; i < end; i++) {
        int u = __ldg(&g_csr[i]);
        float ssh = __ldg(&g_s[(size_t)u * 8 + head]);
        float p = __expf(lrelu(ssh + sdh));
        float4 hv = __ldg((const float4*)(g_h + (size_t)u * F + lane * 4));
        acc.x += p * hv.x; acc.y += p * hv.y;
        acc.z += p * hv.z; acc.w += p * hv.w;
        z += p;
    }
    float inv = 1.f / (z + 1e-16f);
    int col = lane * 4;
    if (mode == 0) {
        float ox = fmaxf(acc.x * inv + b[col], 0.f);
        float oy = fmaxf(acc.y * inv + b[col + 1], 0.f);
        float oz = fmaxf(acc.z * inv + b[col + 2], 0.f);
        float ow = fmaxf(acc.w * inv + b[col + 3], 0.f);
        int kk = col & 31, kt = col >> 5;
        int base = ((kk >> 3) << 1) | ((kk >> 2) & 1);
        uint32_t* p = g_acttf + (size_t)w * F + kt * 32 + base;
        p[0] = f2tf(ox); p[8] = f2tf(oy); p[16] = f2tf(oz); p[24] = f2tf(ow);
    } else {
        float4 bb = *(const float4*)(b + col);
        float4 ww = *(const float4*)(lw + col);
        float s = fmaxf(acc.x * inv + bb.x, 0.f) * ww.x +
                  fmaxf(acc.y * inv + bb.y, 0.f) * ww.y +
                  fmaxf(acc.z * inv + bb.z, 0.f) * ww.z +
                  fmaxf(acc.w * inv + bb.w, 0.f) * ww.w;
        for (int off = 16; off; off >>= 1)
            s += __shfl_xor_sync(0xffffffffu, s, off);
        if (lane == 0) out[w] = s + lb[0];
    }
}

// ---------------- launch ----------------
// Launch #4 (the slot ncu profiles) = gemm128_tc_kernel (layer 1).
extern "C" void kernel_launch(void* const* d_in, const int* in_sizes, int n_in,
                              void* d_out, int out_size)
{
    const float* x   = (const float*)d_in[0];
    const int*   src = (const int*)d_in[1];
    const int*   dst = (const int*)d_in[2];
    const float* W1  = (const float*)d_in[3];
    const float* as1 = (const float*)d_in[4];
    const float* ad1 = (const float*)d_in[5];
    const float* b1  = (const float*)d_in[6];
    const float* W2  = (const float*)d_in[7];
    const float* as2 = (const float*)d_in[8];
    const float* ad2 = (const float*)d_in[9];
    const float* b2  = (const float*)d_in[10];
    const float* lw  = (const float*)d_in[11];
    const float* lb  = (const float*)d_in[12];
    float* out = (float*)d_out;

    int n = in_sizes[0] / F;
    int e = in_sizes[1];

    int nb256 = (n + 255) / 256;
    int eb256 = (e + 255) / 256;
    int ntiles = (n + 1023) / 1024;
    int gemm_blocks = (n + 127) / 128;
    int warp_blocks = (int)(((size_t)n * 32 + 255) / 256);
    int xconv_blocks = (n * 32 + 255) / 256;

    uint32_t* xtf;  cudaGetSymbolAddress((void**)&xtf, g_xtf);
    uint32_t* atf;  cudaGetSymbolAddress((void**)&atf, g_acttf);
    uint32_t* wtf1; cudaGetSymbolAddress((void**)&wtf1, g_Wtf1);
    uint32_t* wtf2; cudaGetSymbolAddress((void**)&wtf2, g_Wtf2);

    wconv_kernel<<<128, 256>>>(W1, W2);                              // 1
    xconv_kernel<<<xconv_blocks, 256>>>(x, n);                       // 2
    cnt_edges_kernel<<<eb256, 256>>>(dst, e);                        // 3
    gemm128_tc_kernel<<<gemm_blocks, 256>>>(xtf, wtf1, as1, ad1, n); // 4 <- profiled
    scan1_kernel<<<ntiles, 1024>>>(n);                               // 5
    scan3_kernel<<<nb256, 256>>>(n);                                 // 6
    fill_kernel<<<eb256, 256>>>(src, dst, e);                        // 7
    agg_kernel<<<warp_blocks, 256>>>(b1, nullptr, nullptr, nullptr, n, 0);  // 8
    gemm128_tc_kernel<<<gemm_blocks, 256>>>(atf, wtf2, as2, ad2, n); // 9
    agg_kernel<<<warp_blocks, 256>>>(b2, lw, lb, out, n, 1);         // 10
}

// round 15
// speedup vs baseline: 1.0811x; 1.0410x over previous
#include <cuda_runtime.h>
#include <cuda_fp16.h>
#include <cstdint>

#define NMAX 50000
#define NPAD (NMAX + 128)
#define EMAX 800000
#define ESLMAX (NMAX + EMAX)
#define F 128
#define NH 4
#define WTF_SZ (4 * 128 * 32)

// ---------------- scratch ----------------
__device__ __half   g_hh[NMAX * F];       // h in fp16 for agg gathers (12.8 MB)
__device__ uint32_t g_xtf[NPAD * F];      // x   tf32 phys [row][kt*32+ph]
__device__ uint32_t g_acttf[NPAD * F];    // act tf32 phys
__device__ float    g_s[NMAX * 8];        // s_src[4], s_dst[4]
__device__ int      g_cnt[NMAX];          // zero at load; scan3 re-zeroes
__device__ int      g_inc[NMAX];
__device__ int      g_tile[64];
__device__ int      g_off[NMAX + 1];
__device__ int      g_cur[NMAX];
__device__ int      g_csr[ESLMAX];
__device__ uint32_t g_Wtf1[WTF_SZ];       // W1 tf32 [kt][n][32] phys
__device__ uint32_t g_Wtf2[WTF_SZ];

__device__ __forceinline__ float lrelu(float x) { return x > 0.f ? x : 0.2f * x; }
__device__ __forceinline__ uint32_t f2tf(float f) {
    uint32_t r; asm("cvt.rna.tf32.f32 %0, %1;" : "=r"(r) : "f"(f)); return r;
}
__device__ __forceinline__ void mma_tf32(float* d, uint32_t a0, uint32_t a1,
                                         uint32_t a2, uint32_t a3,
                                         uint32_t b0, uint32_t b1)
{
    asm volatile(
        "mma.sync.aligned.m16n8k8.row.col.f32.tf32.tf32.f32 "
        "{%0,%1,%2,%3}, {%4,%5,%6,%7}, {%8,%9}, {%0,%1,%2,%3};"
        : "+f"(d[0]), "+f"(d[1]), "+f"(d[2]), "+f"(d[3])
        : "r"(a0), "r"(a1), "r"(a2), "r"(a3), "r"(b0), "r"(b1));
}

// ---------------- prep: xconv + wconv + cnt_edges fused (independent work) ----------------
__global__ void prep_kernel(const float* __restrict__ x,
                            const float* __restrict__ W1,
                            const float* __restrict__ W2,
                            const int* __restrict__ dst,
                            int n, int e, int xconv_blocks)
{
    int b = blockIdx.x;
    if (b < xconv_blocks) {
        // xconv: f32 [row][k] -> tf32 phys [row][kt*32+ph]
        int idx = b * 256 + threadIdx.x;
        if (idx < n * 32) {
            int row = idx >> 5, q = idx & 31;
            float4 v = *(const float4*)(x + (size_t)row * F + q * 4);
            int col = q * 4;
            int kk = col & 31, kt = col >> 5;
            int base = ((kk >> 3) << 1) | ((kk >> 2) & 1);
            uint32_t* p = g_xtf + (size_t)row * F + kt * 32 + base;
            p[0] = f2tf(v.x); p[8] = f2tf(v.y); p[16] = f2tf(v.z); p[24] = f2tf(v.w);
        }
    } else if (b < xconv_blocks + 128) {
        // wconv: f32 [k][n] -> tf32 phys [kt][n][32]
        int idx = (b - xconv_blocks) * 256 + threadIdx.x;   // 0..32767
        int layer = idx >> 14;
        int rem = idx & 16383;
        int kg = rem >> 7, nn = rem & 127;
        const float* W = layer ? W2 : W1;
        float v = W[kg * 128 + nn];
        int kt = kg >> 5, k = kg & 31;
        int ph = (k & 3) * 8 + ((k >> 3) << 1) + ((k >> 2) & 1);
        uint32_t* buf = layer ? g_Wtf2 : g_Wtf1;
        buf[kt * 128 * 32 + nn * 32 + ph] = f2tf(v);
    } else {
        // cnt_edges
        int i = (b - xconv_blocks - 128) * 256 + threadIdx.x;
        if (i < e) atomicAdd(&g_cnt[dst[i]], 1);
    }
}

// ---------------- tf32 GEMM, smem-free; epilogue stores fp16 h + scores ----------------
__global__ __launch_bounds__(256, 2)
void gemm128_tc_kernel(const uint32_t* __restrict__ Atf,
                       const uint32_t* __restrict__ Wtf,
                       const float* __restrict__ asrc,
                       const float* __restrict__ adst, int n)
{
    int tid  = threadIdx.x;
    int warp = tid >> 5, lane = tid & 31;
    int wm = warp >> 1, wn = warp & 1;    // 4x2 warps, warp tile m32 x n64
    int g = lane >> 2, t = lane & 3;
    int row0 = blockIdx.x * 128;

    float acc[2][8][4];
#pragma unroll
    for (int mf = 0; mf < 2; mf++)
#pragma unroll
        for (int i = 0; i < 8; i++)
#pragma unroll
            for (int j = 0; j < 4; j++) acc[mf][i][j] = 0.f;

    const uint32_t* Abase = Atf + (size_t)(row0 + wm * 32 + g) * F + t * 8;
    const uint32_t* Bbase = Wtf + (size_t)(wn * 64 + g) * 32 + t * 8;

#pragma unroll
    for (int kt = 0; kt < 4; kt++) {
        uint4 Aa[2][4];
#pragma unroll
        for (int mf = 0; mf < 2; mf++) {
            const uint32_t* ap = Abase + mf * 16 * F + kt * 32;
            Aa[mf][0] = *(const uint4*)(ap);
            Aa[mf][1] = *(const uint4*)(ap + 4);
            Aa[mf][2] = *(const uint4*)(ap + 8 * F);
            Aa[mf][3] = *(const uint4*)(ap + 8 * F + 4);
        }
#pragma unroll
        for (int nt = 0; nt < 8; nt++) {
            const uint32_t* bp = Bbase + kt * 4096 + nt * 8 * 32;
            uint4 B1 = *(const uint4*)(bp);
            uint4 B2 = *(const uint4*)(bp + 4);
#pragma unroll
            for (int mf = 0; mf < 2; mf++) {
                mma_tf32(acc[mf][nt], Aa[mf][0].x, Aa[mf][2].x, Aa[mf][0].y, Aa[mf][2].y, B1.x, B1.y);
                mma_tf32(acc[mf][nt], Aa[mf][0].z, Aa[mf][2].z, Aa[mf][0].w, Aa[mf][2].w, B1.z, B1.w);
                mma_tf32(acc[mf][nt], Aa[mf][1].x, Aa[mf][3].x, Aa[mf][1].y, Aa[mf][3].y, B2.x, B2.y);
                mma_tf32(acc[mf][nt], Aa[mf][1].z, Aa[mf][3].z, Aa[mf][1].w, Aa[mf][3].w, B2.z, B2.w);
            }
        }
    }

    // epilogue: store h (fp16) + fused attention scores
#pragma unroll
    for (int mf = 0; mf < 2; mf++) {
        int r_lo = row0 + wm * 32 + mf * 16 + g;
        int r_hi = r_lo + 8;
        float ps[2][2] = {{0.f, 0.f}, {0.f, 0.f}};
        float pd[2][2] = {{0.f, 0.f}, {0.f, 0.f}};
#pragma unroll
        for (int nt = 0; nt < 8; nt++) {
            int col = wn * 64 + nt * 8 + 2 * t;
            int hl = nt >> 2;
            float a0s = __ldg(asrc + col), a1s = __ldg(asrc + col + 1);
            float a0d = __ldg(adst + col), a1d = __ldg(adst + col + 1);
            ps[0][hl] += acc[mf][nt][0] * a0s + acc[mf][nt][1] * a1s;
            pd[0][hl] += acc[mf][nt][0] * a0d + acc[mf][nt][1] * a1d;
            ps[1][hl] += acc[mf][nt][2] * a0s + acc[mf][nt][3] * a1s;
            pd[1][hl] += acc[mf][nt][2] * a0d + acc[mf][nt][3] * a1d;
            if (r_lo < n) {
                __half2 hv = __float22half2_rn(make_float2(acc[mf][nt][0], acc[mf][nt][1]));
                *(__half2*)(g_hh + (size_t)r_lo * F + col) = hv;
            }
            if (r_hi < n) {
                __half2 hv = __float22half2_rn(make_float2(acc[mf][nt][2], acc[mf][nt][3]));
                *(__half2*)(g_hh + (size_t)r_hi * F + col) = hv;
            }
        }
#pragma unroll
        for (int off = 1; off <= 2; off <<= 1) {
#pragma unroll
            for (int i = 0; i < 2; i++)
#pragma unroll
                for (int j = 0; j < 2; j++) {
                    ps[i][j] += __shfl_xor_sync(0xffffffffu, ps[i][j], off);
                    pd[i][j] += __shfl_xor_sync(0xffffffffu, pd[i][j], off);
                }
        }
        if (t == 0) {
            int h0 = wn * 2;
            if (r_lo < n) {
                g_s[(size_t)r_lo * 8 + h0]     = ps[0][0];
                g_s[(size_t)r_lo * 8 + h0 + 1] = ps[0][1];
                g_s[(size_t)r_lo * 8 + 4 + h0]     = pd[0][0];
                g_s[(size_t)r_lo * 8 + 4 + h0 + 1] = pd[0][1];
            }
            if (r_hi < n) {
                g_s[(size_t)r_hi * 8 + h0]     = ps[1][0];
                g_s[(size_t)r_hi * 8 + h0 + 1] = ps[1][1];
                g_s[(size_t)r_hi * 8 + 4 + h0]     = pd[1][0];
                g_s[(size_t)r_hi * 8 + 4 + h0 + 1] = pd[1][1];
            }
        }
    }
}

// ---------------- CSR scans ----------------
__global__ void scan1_kernel(int n)
{
    __shared__ int sm[1024];
    int gid = blockIdx.x * 1024 + threadIdx.x;
    int v = (gid < n) ? g_cnt[gid] : 0;
    sm[threadIdx.x] = v;
    __syncthreads();
    for (int off = 1; off < 1024; off <<= 1) {
        int tv = (threadIdx.x >= off) ? sm[threadIdx.x - off] : 0;
        __syncthreads();
        sm[threadIdx.x] += tv;
        __syncthreads();
    }
    if (gid < n) g_inc[gid] = sm[threadIdx.x];
    if (threadIdx.x == 1023) g_tile[blockIdx.x] = sm[1023];
}
__global__ void scan3_kernel(int n)
{
    __shared__ int sm[64];
    int mytile = blockIdx.x >> 2;
    int t = threadIdx.x;
    if (t < 64) sm[t] = (t < mytile) ? g_tile[t] : 0;
    __syncthreads();
    if (t < 32) sm[t] += sm[t + 32];
    __syncthreads();
    if (t < 16) sm[t] += sm[t + 16];
    __syncthreads();
    if (t < 8) sm[t] += sm[t + 8];
    __syncthreads();
    if (t < 4) sm[t] += sm[t + 4];
    __syncthreads();
    if (t < 2) sm[t] += sm[t + 2];
    __syncthreads();
    if (t == 0) sm[0] += sm[1];
    __syncthreads();
    int prefix = sm[0];

    int gid = blockIdx.x * blockDim.x + t;
    if (gid < n) {
        int cnt = g_cnt[gid];
        g_cnt[gid] = 0;                      // restore invariant for next replay
        int val = g_inc[gid] + prefix + gid + 1;   // +gid+1: one self-loop/node
        g_off[gid + 1] = val;
        g_cur[gid] = val - 1 - cnt;
        g_csr[val - 1] = gid;                // self-loop slot
    }
    if (gid == 0) g_off[0] = 0;
}
__global__ void fill_kernel(const int* __restrict__ src,
                            const int* __restrict__ dst, int e)
{
    int i = blockIdx.x * blockDim.x + threadIdx.x;
    if (i >= e) return;
    int pos = atomicAdd(&g_cur[dst[i]], 1);
    g_csr[pos] = src[i];
}

// ---------------- fused softmax + aggregation (fp16 gather) ----------------
// mode 0: g_acttf = tf32-phys(relu(agg + b))   (layer 1 -> GEMM2 input)
// mode 1: out = relu(agg + b) . lw + lb        (layer 2 + readout)
__global__ void agg_kernel(const float* __restrict__ b,
                           const float* __restrict__ lw,
                           const float* __restrict__ lb,
                           float* __restrict__ out, int n, int mode)
{
    int w = (blockIdx.x * blockDim.x + threadIdx.x) >> 5;
    int lane = threadIdx.x & 31;
    if (w >= n) return;
    int beg = g_off[w], end = g_off[w + 1];
    int head = lane >> 3;
    float sdh = g_s[(size_t)w * 8 + 4 + head];

    float4 acc = make_float4(0.f, 0.f, 0.f, 0.f);
    float z = 0.f;
#pragma unroll 4
    for (int i = beg; i < end; i++) {
        int u = __ldg(&g_csr[i]);
        float ssh = __ldg(&g_s[(size_t)u * 8 + head]);
        float p = __expf(lrelu(ssh + sdh));
        uint2 raw = __ldg((const uint2*)(g_hh + (size_t)u * F + lane * 4));
        float2 f01 = __half22float2(*reinterpret_cast<__half2*>(&raw.x));
        float2 f23 = __half22float2(*reinterpret_cast<__half2*>(&raw.y));
        acc.x += p * f01.x; acc.y += p * f01.y;
        acc.z += p * f23.x; acc.w += p * f23.y;
        z += p;
    }
    float inv = 1.f / (z + 1e-16f);
    int col = lane * 4;
    if (mode == 0) {
        float ox = fmaxf(acc.x * inv + b[col], 0.f);
        float oy = fmaxf(acc.y * inv + b[col + 1], 0.f);
        float oz = fmaxf(acc.z * inv + b[col + 2], 0.f);
        float ow = fmaxf(acc.w * inv + b[col + 3], 0.f);
        int kk = col & 31, kt = col >> 5;
        int base = ((kk >> 3) << 1) | ((kk >> 2) & 1);
        uint32_t* p2 = g_acttf + (size_t)w * F + kt * 32 + base;
        p2[0] = f2tf(ox); p2[8] = f2tf(oy); p2[16] = f2tf(oz); p2[24] = f2tf(ow);
    } else {
        float4 bb = *(const float4*)(b + col);
        float4 ww = *(const float4*)(lw + col);
        float s = fmaxf(acc.x * inv + bb.x, 0.f) * ww.x +
                  fmaxf(acc.y * inv + bb.y, 0.f) * ww.y +
                  fmaxf(acc.z * inv + bb.z, 0.f) * ww.z +
                  fmaxf(acc.w * inv + bb.w, 0.f) * ww.w;
        for (int off = 16; off; off >>= 1)
            s += __shfl_xor_sync(0xffffffffu, s, off);
        if (lane == 0) out[w] = s + lb[0];
    }
}

// ---------------- launch ----------------
// Slot #4 (the one ncu profiles) = gemm128_tc_kernel (layer 1).
extern "C" void kernel_launch(void* const* d_in, const int* in_sizes, int n_in,
                              void* d_out, int out_size)
{
    const float* x   = (const float*)d_in[0];
    const int*   src = (const int*)d_in[1];
    const int*   dst = (const int*)d_in[2];
    const float* W1  = (const float*)d_in[3];
    const float* as1 = (const float*)d_in[4];
    const float* ad1 = (const float*)d_in[5];
    const float* b1  = (const float*)d_in[6];
    const float* W2  = (const float*)d_in[7];
    const float* as2 = (const float*)d_in[8];
    const float* ad2 = (const float*)d_in[9];
    const float* b2  = (const float*)d_in[10];
    const float* lw  = (const float*)d_in[11];
    const float* lb  = (const float*)d_in[12];
    float* out = (float*)d_out;

    int n = in_sizes[0] / F;
    int e = in_sizes[1];

    int nb256 = (n + 255) / 256;
    int eb256 = (e + 255) / 256;
    int ntiles = (n + 1023) / 1024;
    int gemm_blocks = (n + 127) / 128;
    int warp_blocks = (int)(((size_t)n * 32 + 255) / 256);
    int xconv_blocks = (n * 32 + 255) / 256;
    int prep_blocks = xconv_blocks + 128 + eb256;

    uint32_t* xtf;  cudaGetSymbolAddress((void**)&xtf, g_xtf);
    uint32_t* atf;  cudaGetSymbolAddress((void**)&atf, g_acttf);
    uint32_t* wtf1; cudaGetSymbolAddress((void**)&wtf1, g_Wtf1);
    uint32_t* wtf2; cudaGetSymbolAddress((void**)&wtf2, g_Wtf2);

    prep_kernel<<<prep_blocks, 256>>>(x, W1, W2, dst, n, e, xconv_blocks);   // 1
    scan1_kernel<<<ntiles, 1024>>>(n);                                       // 2
    scan3_kernel<<<nb256, 256>>>(n);                                         // 3
    gemm128_tc_kernel<<<gemm_blocks, 256>>>(xtf, wtf1, as1, ad1, n);         // 4 <- profiled
    fill_kernel<<<eb256, 256>>>(src, dst, e);                                // 5
    agg_kernel<<<warp_blocks, 256>>>(b1, nullptr, nullptr, nullptr, n, 0);   // 6
    gemm128_tc_kernel<<<gemm_blocks, 256>>>(atf, wtf2, as2, ad2, n);         // 7
    agg_kernel<<<warp_blocks, 256>>>(b2, lw, lb, out, n, 1);                 // 8
}